// round 2
// baseline (speedup 1.0000x reference)
#include <cuda_runtime.h>

#define NPOS 9
#define NROWS 16384      // T*B = 512*32
#define D 128
#define TILE_ROWS 64
#define MAX_CHUNKS 264   // 256 + (9-1); provable upper bound on total chunk count

__device__ int g_count[NPOS];          // zero-init; plan_kernel re-zeros each call
__device__ int g_cnt[NPOS];
__device__ int g_prefix[NPOS + 1];
__device__ int g_list[NPOS * NROWS];

// ---------------------------------------------------------------------------
// Kernel 1: group rows by clipped position (CTA-aggregated atomics).
// Per-CTA dtype detection: scan 256 int32 words in-bounds under BOTH
// int32/int64 interpretations; int64 => all odd words are zero high-words.
// ---------------------------------------------------------------------------
__global__ void build_lists(const void* __restrict__ pos_raw) {
    __shared__ int s_cnt[NPOS];
    __shared__ int s_base[NPOS];
    const int* pos32 = (const int*)pos_raw;
    int tid = threadIdx.x;
    if (tid < NPOS) s_cnt[tid] = 0;

    // dtype probe: words [b*256, b*256+256) are always valid
    int w = pos32[blockIdx.x * 256 + tid];
    int found = (tid & 1) && (w != 0);
    int is32 = __syncthreads_or(found);   // also covers the s_cnt init barrier

    int row = blockIdx.x * 256 + tid;     // grid covers exactly NROWS
    int p;
    if (is32) {
        p = pos32[row];
    } else {
        p = (int)((const long long*)pos_raw)[row];
    }
    int r = (p < 8) ? p : 8;
    int local = atomicAdd(&s_cnt[r], 1);
    __syncthreads();

    if (tid < NPOS) s_base[tid] = atomicAdd(&g_count[tid], s_cnt[tid]);
    __syncthreads();

    g_list[r * NROWS + s_base[r] + local] = row;
}

// ---------------------------------------------------------------------------
// Kernel 2: chunk prefix plan; resets g_count so every call starts clean
// ---------------------------------------------------------------------------
__global__ void plan_kernel() {
    int pre = 0;
    for (int p = 0; p < NPOS; p++) {
        int c = g_count[p];
        g_cnt[p] = c;
        g_prefix[p] = pre;
        pre += (c + TILE_ROWS - 1) / TILE_ROWS;
        g_count[p] = 0;
    }
    g_prefix[NPOS] = pre;
}

// ---------------------------------------------------------------------------
// Kernel 3: per-group skinny GEMM. Tile: 64 rows x 128 cols, K = 128.
// M (128x128 f32, 64KB) + X (64x128 f32, 32KB) in smem. Each thread owns
// 8 rows x 4 cols, inner product via packed fma.rn.f32x2 (2 FMA/instr).
// ---------------------------------------------------------------------------
__global__ void __launch_bounds__(256, 2)
transfer_gemm(const float* __restrict__ x,
              const float* __restrict__ table,
              float* __restrict__ out) {
    extern __shared__ float smem[];
    float* Ms = smem;                 // [128][128]
    float* Xs = smem + D * D;         // [64][128]

    int cid = blockIdx.x;
    if (cid >= g_prefix[NPOS]) return;

    // locate group p for this flat chunk id
    int p = 0;
    #pragma unroll
    for (int i = 1; i < NPOS; i++)
        if (g_prefix[i] <= cid) p = i;
    int chunk = cid - g_prefix[p];

    int cnt = g_cnt[p];
    int row0 = chunk * TILE_ROWS;
    int nrows = cnt - row0;
    if (nrows > TILE_ROWS) nrows = TILE_ROWS;
    const int* list = g_list + p * NROWS + row0;

    int tid = threadIdx.x;

    // load M = table[p] (4096 float4, 16 per thread)
    {
        const float4* Mg = (const float4*)(table + p * D * D);
        float4* Msv = (float4*)Ms;
        #pragma unroll
        for (int i = 0; i < 16; i++)
            Msv[tid + i * 256] = Mg[tid + i * 256];
    }
    // gather X rows (each row = 32 float4 contiguous in gmem)
    for (int i = tid; i < TILE_ROWS * 32; i += 256) {
        int rl = i >> 5;
        int c  = i & 31;
        if (rl < nrows) {
            int row = list[rl];
            ((float4*)Xs)[i] = ((const float4*)(x + row * D))[c];
        }
    }
    __syncthreads();

    int lane = tid & 31;        // column group: cols [4*lane, 4*lane+3]
    int wrp  = tid >> 5;        // row group: rows [8*wrp, 8*wrp+7]
    const float* Mp = Ms + lane * 4;
    const float* Xp = Xs + wrp * 8 * D;

    unsigned long long acc01[8], acc23[8];
    #pragma unroll
    for (int j = 0; j < 8; j++) { acc01[j] = 0ull; acc23[j] = 0ull; }

    for (int d = 0; d < D; d += 4) {
        float xr[8][4];
        #pragma unroll
        for (int j = 0; j < 8; j++) {
            float4 v = *(const float4*)(Xp + j * D + d);   // warp-uniform broadcast
            xr[j][0] = v.x; xr[j][1] = v.y; xr[j][2] = v.z; xr[j][3] = v.w;
        }
        #pragma unroll
        for (int dd = 0; dd < 4; dd++) {
            float4 m = *(const float4*)(Mp + (d + dd) * D); // 4-phase conflict-free
            unsigned long long m01, m23;
            asm("mov.b64 %0, {%1, %2};" : "=l"(m01) : "f"(m.x), "f"(m.y));
            asm("mov.b64 %0, {%1, %2};" : "=l"(m23) : "f"(m.z), "f"(m.w));
            #pragma unroll
            for (int j = 0; j < 8; j++) {
                unsigned long long xx;
                asm("mov.b64 %0, {%1, %1};" : "=l"(xx) : "f"(xr[j][dd]));
                asm("fma.rn.f32x2 %0, %1, %2, %0;" : "+l"(acc01[j]) : "l"(m01), "l"(xx));
                asm("fma.rn.f32x2 %0, %1, %2, %0;" : "+l"(acc23[j]) : "l"(m23), "l"(xx));
            }
        }
    }

    #pragma unroll
    for (int j = 0; j < 8; j++) {
        int rl = wrp * 8 + j;
        if (rl < nrows) {
            int row = list[rl];
            float a0, a1, a2, a3;
            asm("mov.b64 {%0, %1}, %2;" : "=f"(a0), "=f"(a1) : "l"(acc01[j]));
            asm("mov.b64 {%0, %1}, %2;" : "=f"(a2), "=f"(a3) : "l"(acc23[j]));
            float4 o; o.x = a0; o.y = a1; o.z = a2; o.w = a3;
            *(float4*)(out + row * D + lane * 4) = o;
        }
    }
}

// ---------------------------------------------------------------------------
extern "C" void kernel_launch(void* const* d_in, const int* in_sizes, int n_in,
                              void* d_out, int out_size) {
    const void*  positions = d_in[0];                 // int32 or int64 [T,B] (auto-detected)
    const float* outputs   = (const float*)d_in[1];   // f32 [T,B,128]
    const float* table     = (const float*)d_in[2];   // f32 [9,128,128]
    float*       out       = (float*)d_out;           // f32 [T,B,128]
    (void)in_sizes; (void)n_in; (void)out_size;

    static const int SMEM_BYTES = (D * D + TILE_ROWS * D) * (int)sizeof(float); // 98304
    // runs once, on the first (non-captured) correctness call
    static cudaError_t attr_once = cudaFuncSetAttribute(
        transfer_gemm, cudaFuncAttributeMaxDynamicSharedMemorySize, SMEM_BYTES);
    (void)attr_once;

    build_lists<<<NROWS / 256, 256>>>(positions);
    plan_kernel<<<1, 1>>>();
    transfer_gemm<<<MAX_CHUNKS, 256, SMEM_BYTES>>>(outputs, table, out);
}